// round 4
// baseline (speedup 1.0000x reference)
#include <cuda_runtime.h>
#include <math.h>
#include <float.h>

#define Bb   2
#define Qn   900
#define Cn   256
#define Ncam 6
#define NP   (Bb*Ncam*Qn)   // 10800
#define BQ   (Bb*Qn)        // 1800

// ---------------- scratch (static device globals; no allocation) -------------
__device__ float  g_inv[Bb*Ncam*16];
__device__ int    g_count;
__device__ int    g_map[NP];       // p -> slot or -1
__device__ float4 g_projc[NP];     // per slot: ix, iy, cam, unused
__device__ float  g_ms[NP*Cn];     // compacted sampled features
__device__ float  g_v [NP*Cn];     // compacted v rows
__device__ float  g_q [BQ*Cn];
__device__ float  g_fu[BQ*Cn];

// ---------------- K1: batched 4x4 inverse (double, partial pivot) ------------
__global__ void invert_kernel(const float* __restrict__ ext) {
    int t = threadIdx.x;
    if (t == 0) g_count = 0;
    if (t >= Bb*Ncam) return;
    const float* E = ext + t*16;
    double a[4][8];
    for (int i = 0; i < 4; i++)
        for (int j = 0; j < 4; j++) { a[i][j] = (double)E[i*4+j]; a[i][4+j] = (i==j) ? 1.0 : 0.0; }
    for (int c = 0; c < 4; c++) {
        int p = c; double mv = fabs(a[c][c]);
        for (int r = c+1; r < 4; r++) { double v = fabs(a[r][c]); if (v > mv) { mv = v; p = r; } }
        if (p != c) for (int j = 0; j < 8; j++) { double tmp = a[c][j]; a[c][j] = a[p][j]; a[p][j] = tmp; }
        double ip = 1.0 / a[c][c];
        for (int j = 0; j < 8; j++) a[c][j] *= ip;
        for (int r = 0; r < 4; r++) if (r != c) {
            double f = a[r][c];
            for (int j = 0; j < 8; j++) a[r][j] -= f * a[c][j];
        }
    }
    for (int i = 0; i < 4; i++)
        for (int j = 0; j < 4; j++) {
            float f = (float)a[i][4+j];
            if (isnan(f)) f = 0.0f;
            else if (isinf(f)) f = (f > 0.f) ? 1e6f : -1e6f;
            g_inv[t*16 + i*4 + j] = f;
        }
}

// ---------------- K2: project + candidate compaction --------------------------
__global__ void project_kernel(const float* __restrict__ refpts,
                               const int*   __restrict__ mask,
                               const float* __restrict__ intr) {
    int p = blockIdx.x * blockDim.x + threadIdx.x;
    if (p >= NP) return;
    int b = p / (Ncam*Qn);
    int n = (p / Qn) % Ncam;
    int q = p % Qn;
    int bq = b*Qn + q;
    if (mask[bq] != 0) { g_map[p] = -1; return; }

    float r0 = refpts[bq*3+0] * 102.4f - 51.2f;
    float r1 = refpts[bq*3+1] * 102.4f - 51.2f;
    float r2 = refpts[bq*3+2] * 102.4f - 51.2f;

    const float* iv = g_inv + (b*Ncam + n)*16;
    float p0 = iv[0]*r0 + iv[1]*r1 + iv[2]*r2  + iv[3];
    float p1 = iv[4]*r0 + iv[5]*r1 + iv[6]*r2  + iv[7];
    float p2 = iv[8]*r0 + iv[9]*r1 + iv[10]*r2 + iv[11];

    float depth = p2;
    if (isnan(depth)) depth = 10.0f;
    else if (isinf(depth)) depth = (depth > 0.f) ? 100.0f : -100.0f;
    bool invalid = depth < 1.5f;
    float ds = fmaxf(depth, 1.5f);

    float cx = p0 / ds, cy = p1 / ds, cz = p2 / ds;
    const float* Km = intr + (b*Ncam + n)*9;
    float ix = Km[0]*cx + Km[1]*cy + Km[2]*cz;
    float iy = Km[3]*cx + Km[4]*cy + Km[5]*cz;
    ix = fminf(fmaxf(ix, -3000.f), 3000.f);
    iy = fminf(fmaxf(iy, -3000.f), 3000.f);

    // exact union of per-level corner-valid regions == level-3 (W=25,H=14) box
    bool cand = !invalid && (ix >= -32.f) && (ix < 800.f) && (iy >= -32.f) && (iy < 448.f);
    int slot = -1;
    if (cand) {
        slot = atomicAdd(&g_count, 1);
        g_projc[slot] = make_float4(ix, iy, (float)(b*Ncam + n), 0.f);
    }
    g_map[p] = slot;
}

// ---------------- GEMM core: BM=64, BN=64, BK=32, 128 threads, 4x8 utile -----
__device__ __forceinline__ void gemm_core(
    const float* __restrict__ A, const float* __restrict__ Wt,
    const float* __restrict__ bias, float* __restrict__ Cmat,
    int M, int bm, int bn, const int* __restrict__ omask,
    float (*As)[68], float (*Bs)[68])
{
    int tid = threadIdx.x;
    int tx = tid & 7;    // n: 8 cols of 8
    int ty = tid >> 3;   // m: 16 rows of 4
    float acc[4][8];
#pragma unroll
    for (int i = 0; i < 4; i++)
#pragma unroll
        for (int j = 0; j < 8; j++) acc[i][j] = 0.f;

    for (int k0 = 0; k0 < 256; k0 += 32) {
#pragma unroll
        for (int t = 0; t < 4; t++) {
            int id = tid + t*128;
            int row = id >> 3;
            int kq = (id & 7) * 4;
            int m = bm + row;
            float4 v = make_float4(0.f,0.f,0.f,0.f);
            if (m < M) v = *(const float4*)(A + (long)m*256 + k0 + kq);
            As[kq+0][row] = v.x; As[kq+1][row] = v.y;
            As[kq+2][row] = v.z; As[kq+3][row] = v.w;
        }
#pragma unroll
        for (int t = 0; t < 4; t++) {
            int id = tid + t*128;
            int row = id >> 3;
            int kq = (id & 7) * 4;
            float4 v = *(const float4*)(Wt + (long)(bn + row)*256 + k0 + kq);
            Bs[kq+0][row] = v.x; Bs[kq+1][row] = v.y;
            Bs[kq+2][row] = v.z; Bs[kq+3][row] = v.w;
        }
        __syncthreads();
#pragma unroll
        for (int k = 0; k < 32; k++) {
            float4 av = *(const float4*)&As[k][ty*4];
            float4 b0 = *(const float4*)&Bs[k][tx*8];
            float4 b1 = *(const float4*)&Bs[k][tx*8 + 4];
            float am[4] = {av.x, av.y, av.z, av.w};
            float bv[8] = {b0.x, b0.y, b0.z, b0.w, b1.x, b1.y, b1.z, b1.w};
#pragma unroll
            for (int i = 0; i < 4; i++)
#pragma unroll
                for (int j = 0; j < 8; j++) acc[i][j] += am[i] * bv[j];
        }
        __syncthreads();
    }

    float4 bia0 = *(const float4*)(bias + bn + tx*8);
    float4 bia1 = *(const float4*)(bias + bn + tx*8 + 4);
#pragma unroll
    for (int i = 0; i < 4; i++) {
        int m = bm + ty*4 + i;
        if (m < M) {
            float4 o0, o1;
            o0.x = acc[i][0] + bia0.x; o0.y = acc[i][1] + bia0.y;
            o0.z = acc[i][2] + bia0.z; o0.w = acc[i][3] + bia0.w;
            o1.x = acc[i][4] + bia1.x; o1.y = acc[i][5] + bia1.y;
            o1.z = acc[i][6] + bia1.z; o1.w = acc[i][7] + bia1.w;
            if (omask && omask[m] != 0) {
                o0 = make_float4(0.f,0.f,0.f,0.f);
                o1 = make_float4(0.f,0.f,0.f,0.f);
            }
            *(float4*)(Cmat + (long)m*256 + bn + tx*8)     = o0;
            *(float4*)(Cmat + (long)m*256 + bn + tx*8 + 4) = o1;
        }
    }
}

// ---------------- K3: fused [q-GEMM | bilinear sampling] ----------------------
#define GQ_TILES_M ((BQ + 63)/64)            // 29
#define GQ_BLOCKS  (GQ_TILES_M * 4)          // 116
#define SAMP_BLOCKS 296

__constant__ int c_H[4] = {112, 56, 28, 14};
__constant__ int c_W[4] = {200, 100, 50, 25};

__global__ __launch_bounds__(128) void fused_qsample_kernel(
    const float* __restrict__ query, const float* __restrict__ Wq,
    const float* __restrict__ bq,
    const float* __restrict__ f0, const float* __restrict__ f1,
    const float* __restrict__ f2, const float* __restrict__ f3)
{
    __shared__ float As[32][68];
    __shared__ float Bs[32][68];
    int bid = blockIdx.x;
    if (bid < GQ_BLOCKS) {
        int bm = (bid >> 2) * 64;
        int bn = (bid & 3) * 64;
        gemm_core(query, Wq, bq, g_q, BQ, bm, bn, nullptr, As, Bs);
        return;
    }
    // -------- sampling path (persistent over compacted points) --------
    int cnt = g_count;
    const float* fp[4] = {f0, f1, f2, f3};
    for (int i = bid - GQ_BLOCKS; i < cnt; i += SAMP_BLOCKS) {
        float4 pc = g_projc[i];
        float X = pc.x, Y = pc.y;
        int cam = (int)pc.z;

        int   off[4][4];
        float wei[4][4];
#pragma unroll
        for (int l = 0; l < 4; l++) {
            int H = c_H[l], W = c_W[l];
            float fx = X * ((float)W / 800.0f);
            float fy = Y * ((float)H / 448.0f);
            float gx = fminf(fmaxf(fx / (float)(W-1) * 2.0f - 1.0f, -10.f), 10.f);
            float gy = fminf(fmaxf(fy / (float)(H-1) * 2.0f - 1.0f, -10.f), 10.f);
            float px = (gx + 1.0f) * 0.5f * (float)(W-1);
            float py = (gy + 1.0f) * 0.5f * (float)(H-1);
            float x0f = floorf(px), y0f = floorf(py);
            int x0 = (int)x0f, y0 = (int)y0f;
            float wx = px - x0f, wy = py - y0f;
            bool vx0 = (x0 >= 0)   && (x0 < W);
            bool vx1 = (x0+1 >= 0) && (x0+1 < W);
            bool vy0 = (y0 >= 0)   && (y0 < H);
            bool vy1 = (y0+1 >= 0) && (y0+1 < H);
            int xc0 = min(max(x0, 0), W-1),  xc1 = min(max(x0+1, 0), W-1);
            int yc0 = min(max(y0, 0), H-1),  yc1 = min(max(y0+1, 0), H-1);
            off[l][0] = (vy0 && vx0) ? yc0*W + xc0 : -1;
            off[l][1] = (vy0 && vx1) ? yc0*W + xc1 : -1;
            off[l][2] = (vy1 && vx0) ? yc1*W + xc0 : -1;
            off[l][3] = (vy1 && vx1) ? yc1*W + xc1 : -1;
            wei[l][0] = (1.f-wx)*(1.f-wy);
            wei[l][1] = wx*(1.f-wy);
            wei[l][2] = (1.f-wx)*wy;
            wei[l][3] = wx*wy;
        }
#pragma unroll
        for (int cc = 0; cc < 2; cc++) {
            int c = threadIdx.x + cc*128;
            float acc = 0.f;
#pragma unroll
            for (int l = 0; l < 4; l++) {
                int HW = c_H[l] * c_W[l];
                const float* base = fp[l] + (long)(cam*Cn + c) * HW;
#pragma unroll
                for (int r = 0; r < 4; r++) {
                    int o = off[l][r];
                    if (o >= 0) acc += __ldg(base + o) * wei[l][r];
                }
            }
            g_ms[(long)i*Cn + c] = acc * 0.25f;
        }
    }
}

// ---------------- K4: v-GEMM over compacted rows ------------------------------
__global__ __launch_bounds__(128) void vgemm_kernel(
    const float* __restrict__ Wv, const float* __restrict__ bv)
{
    __shared__ float As[32][68];
    __shared__ float Bs[32][68];
    int M = g_count;
    int bm = blockIdx.y * 64;
    if (bm >= M) return;
    int bn = blockIdx.x * 64;
    gemm_core(g_ms, Wv, bv, g_v, M, bm, bn, nullptr, As, Bs);
}

// ---------------- K5: max over cameras + fuse --------------------------------
__global__ void maxfuse_kernel(const float* __restrict__ bv) {
    int bq = blockIdx.x;
    int c = threadIdx.x;
    int b = bq / Qn, q = bq % Qn;
    __shared__ int slots[Ncam];
    if (c < Ncam) slots[c] = g_map[(b*Ncam + c)*Qn + q];
    __syncthreads();
    float bvv = __ldg(bv + c);
    float m = -FLT_MAX;
#pragma unroll
    for (int n = 0; n < Ncam; n++) {
        int s = slots[n];
        float v = (s >= 0) ? g_v[(long)s*Cn + c] : bvv;
        m = fmaxf(m, v);
    }
    float qv = g_q[(long)bq*Cn + c];
    g_fu[(long)bq*Cn + c] = fmaxf(qv + m, 0.f) + qv;
}

// ---------------- K6: o-GEMM -------------------------------------------------
__global__ __launch_bounds__(128) void ogemm_kernel(
    const float* __restrict__ Wo, const float* __restrict__ bo,
    float* __restrict__ out, const int* __restrict__ mask)
{
    __shared__ float As[32][68];
    __shared__ float Bs[32][68];
    int bm = blockIdx.y * 64;
    int bn = blockIdx.x * 64;
    gemm_core(g_fu, Wo, bo, out, BQ, bm, bn, mask, As, Bs);
}

// ---------------- launch ------------------------------------------------------
extern "C" void kernel_launch(void* const* d_in, const int* in_sizes, int n_in,
                              void* d_out, int out_size) {
    const float* query  = (const float*)d_in[0];
    const float* refpts = (const float*)d_in[1];
    const int*   mask   = (const int*)  d_in[2];
    const float* intr   = (const float*)d_in[3];
    const float* ext    = (const float*)d_in[4];
    const float* f0     = (const float*)d_in[5];
    const float* f1     = (const float*)d_in[6];
    const float* f2     = (const float*)d_in[7];
    const float* f3     = (const float*)d_in[8];
    const float* Wq     = (const float*)d_in[9];
    const float* bq     = (const float*)d_in[10];
    const float* Wv     = (const float*)d_in[11];
    const float* bv     = (const float*)d_in[12];
    const float* Wo     = (const float*)d_in[13];
    const float* bo     = (const float*)d_in[14];

    invert_kernel<<<1, 32>>>(ext);
    project_kernel<<<(NP + 127)/128, 128>>>(refpts, mask, intr);
    fused_qsample_kernel<<<GQ_BLOCKS + SAMP_BLOCKS, 128>>>(query, Wq, bq, f0, f1, f2, f3);
    vgemm_kernel<<<dim3(4, (NP + 63)/64), 128>>>(Wv, bv);
    maxfuse_kernel<<<BQ, Cn>>>(bv);
    ogemm_kernel<<<dim3(4, (BQ + 63)/64), 128>>>(Wo, bo, (float*)d_out, mask);
}

// round 6
// speedup vs baseline: 1.3267x; 1.3267x over previous
#include <cuda_runtime.h>
#include <cuda_bf16.h>
#include <math.h>
#include <float.h>

#define Bb   2
#define Qn   900
#define Cn   256
#define Ncam 6
#define NP   (Bb*Ncam*Qn)   // 10800
#define BQ   (Bb*Qn)        // 1800

// ---------------- scratch (static device globals; no allocation) -------------
__device__ float  g_inv[Bb*Ncam*16];
__device__ int    g_count;
__device__ int    g_map[NP];
__device__ float4 g_projc[NP];
__device__ float  g_ms[NP*Cn];
__device__ float  g_v [NP*Cn];
__device__ float  g_q [BQ*Cn];
__device__ float  g_fu[BQ*Cn];
// packed split weights, layout [kpair][n]: word kp*256+n packs bf16(W[n][2kp]),bf16(W[n][2kp+1])
__device__ unsigned g_WH[3][128*256];
__device__ unsigned g_WL[3][128*256];

// ---------------- K1: batched 4x4 inverse (double, partial pivot) ------------
__global__ void invert_kernel(const float* __restrict__ ext) {
    int t = threadIdx.x;
    if (t == 0) g_count = 0;
    if (t >= Bb*Ncam) return;
    const float* E = ext + t*16;
    double a[4][8];
    for (int i = 0; i < 4; i++)
        for (int j = 0; j < 4; j++) { a[i][j] = (double)E[i*4+j]; a[i][4+j] = (i==j) ? 1.0 : 0.0; }
    for (int c = 0; c < 4; c++) {
        int p = c; double mv = fabs(a[c][c]);
        for (int r = c+1; r < 4; r++) { double v = fabs(a[r][c]); if (v > mv) { mv = v; p = r; } }
        if (p != c) for (int j = 0; j < 8; j++) { double tmp = a[c][j]; a[c][j] = a[p][j]; a[p][j] = tmp; }
        double ip = 1.0 / a[c][c];
        for (int j = 0; j < 8; j++) a[c][j] *= ip;
        for (int r = 0; r < 4; r++) if (r != c) {
            double f = a[r][c];
            for (int j = 0; j < 8; j++) a[r][j] -= f * a[c][j];
        }
    }
    for (int i = 0; i < 4; i++)
        for (int j = 0; j < 4; j++) {
            float f = (float)a[i][4+j];
            if (isnan(f)) f = 0.0f;
            else if (isinf(f)) f = (f > 0.f) ? 1e6f : -1e6f;
            g_inv[t*16 + i*4 + j] = f;
        }
}

// ---------------- weight split/pack ------------------------------------------
__global__ void prep_weights(const float* __restrict__ Wq,
                             const float* __restrict__ Wv,
                             const float* __restrict__ Wo) {
    int idx = blockIdx.x * blockDim.x + threadIdx.x;
    if (idx >= 3*128*256) return;
    int w   = idx / (128*256);
    int rem = idx % (128*256);
    int kp  = rem / 256;
    int n   = rem % 256;
    const float* W = (w==0) ? Wq : ((w==1) ? Wv : Wo);
    float a = W[n*256 + kp*2], b = W[n*256 + kp*2 + 1];
    __nv_bfloat16 ah = __float2bfloat16(a), bh = __float2bfloat16(b);
    __nv_bfloat16 al = __float2bfloat16(a - __bfloat162float(ah));
    __nv_bfloat16 bl = __float2bfloat16(b - __bfloat162float(bh));
    g_WH[w][rem] = (unsigned)__bfloat16_as_ushort(ah) | ((unsigned)__bfloat16_as_ushort(bh) << 16);
    g_WL[w][rem] = (unsigned)__bfloat16_as_ushort(al) | ((unsigned)__bfloat16_as_ushort(bl) << 16);
}

// ---------------- K2: project + candidate compaction --------------------------
__global__ void project_kernel(const float* __restrict__ refpts,
                               const int*   __restrict__ mask,
                               const float* __restrict__ intr) {
    int p = blockIdx.x * blockDim.x + threadIdx.x;
    if (p >= NP) return;
    int b = p / (Ncam*Qn);
    int n = (p / Qn) % Ncam;
    int q = p % Qn;
    int bq = b*Qn + q;
    if (mask[bq] != 0) { g_map[p] = -1; return; }

    float r0 = refpts[bq*3+0] * 102.4f - 51.2f;
    float r1 = refpts[bq*3+1] * 102.4f - 51.2f;
    float r2 = refpts[bq*3+2] * 102.4f - 51.2f;

    const float* iv = g_inv + (b*Ncam + n)*16;
    float p0 = iv[0]*r0 + iv[1]*r1 + iv[2]*r2  + iv[3];
    float p1 = iv[4]*r0 + iv[5]*r1 + iv[6]*r2  + iv[7];
    float p2 = iv[8]*r0 + iv[9]*r1 + iv[10]*r2 + iv[11];

    float depth = p2;
    if (isnan(depth)) depth = 10.0f;
    else if (isinf(depth)) depth = (depth > 0.f) ? 100.0f : -100.0f;
    bool invalid = depth < 1.5f;
    float ds = fmaxf(depth, 1.5f);

    float cx = p0 / ds, cy = p1 / ds, cz = p2 / ds;
    const float* Km = intr + (b*Ncam + n)*9;
    float ix = Km[0]*cx + Km[1]*cy + Km[2]*cz;
    float iy = Km[3]*cx + Km[4]*cy + Km[5]*cz;
    ix = fminf(fmaxf(ix, -3000.f), 3000.f);
    iy = fminf(fmaxf(iy, -3000.f), 3000.f);

    bool cand = !invalid && (ix >= -32.f) && (ix < 800.f) && (iy >= -32.f) && (iy < 448.f);
    int slot = -1;
    if (cand) {
        slot = atomicAdd(&g_count, 1);
        g_projc[slot] = make_float4(ix, iy, (float)(b*Ncam + n), 0.f);
    }
    g_map[p] = slot;
}

// ---------------- tensor-core split-bf16 GEMM --------------------------------
// C[M,256] = A[M,256] @ W[256,256]^T + bias. BM=64,BN=64,BK=32, 256 thr, 8 warps.
__device__ __forceinline__ void mma_bf16(float& d0, float& d1, float& d2, float& d3,
    unsigned a0, unsigned a1, unsigned a2, unsigned a3, unsigned b0, unsigned b1) {
    asm volatile("mma.sync.aligned.m16n8k16.row.col.f32.bf16.bf16.f32 "
        "{%0,%1,%2,%3}, {%4,%5,%6,%7}, {%8,%9}, {%0,%1,%2,%3};"
        : "+f"(d0), "+f"(d1), "+f"(d2), "+f"(d3)
        : "r"(a0), "r"(a1), "r"(a2), "r"(a3), "r"(b0), "r"(b1));
}

__device__ __forceinline__ void split2(float a, float b, unsigned& h, unsigned& l) {
    __nv_bfloat16 ah = __float2bfloat16(a), bh = __float2bfloat16(b);
    __nv_bfloat16 al = __float2bfloat16(a - __bfloat162float(ah));
    __nv_bfloat16 bl = __float2bfloat16(b - __bfloat162float(bh));
    h = (unsigned)__bfloat16_as_ushort(ah) | ((unsigned)__bfloat16_as_ushort(bh) << 16);
    l = (unsigned)__bfloat16_as_ushort(al) | ((unsigned)__bfloat16_as_ushort(bl) << 16);
}

__global__ __launch_bounds__(256) void tgemm_kernel(
    const float* __restrict__ A, int widx, const float* __restrict__ bias,
    float* __restrict__ C, int M, int dynM, const int* __restrict__ omask)
{
    if (dynM) M = g_count;
    int bm = blockIdx.y * 64;
    if (bm >= M) return;
    int bn = blockIdx.x * 64;

    __shared__ unsigned AsH[64][20], AsL[64][20];   // [m][kpair], pad->20 (conflict-free)
    __shared__ unsigned BsH[16][72], BsL[16][72];   // [kpair][n], pad->72 (conflict-free)

    const unsigned* __restrict__ WH = g_WH[widx];
    const unsigned* __restrict__ WL = g_WL[widx];

    int tid  = threadIdx.x;
    int lane = tid & 31, warp = tid >> 5;
    int wm = (warp & 3) * 16, wn = (warp >> 2) * 32;
    int ld4 = lane >> 2, lp4 = lane & 3;

    float acc[4][4];
#pragma unroll
    for (int i = 0; i < 4; i++)
#pragma unroll
        for (int j = 0; j < 4; j++) acc[i][j] = 0.f;

    for (int kt = 0; kt < 8; kt++) {
        // ---- fill A tile (fp32 -> split bf16 pairs) ----
#pragma unroll
        for (int t = 0; t < 2; t++) {
            int id = tid + t*256;
            int m = id >> 3, q = id & 7;
            float4 v = make_float4(0.f, 0.f, 0.f, 0.f);
            if (bm + m < M) v = *(const float4*)(A + (long)(bm + m)*256 + kt*32 + q*4);
            unsigned h0, l0, h1, l1;
            split2(v.x, v.y, h0, l0);
            split2(v.z, v.w, h1, l1);
            *(uint2*)&AsH[m][q*2] = make_uint2(h0, h1);
            *(uint2*)&AsL[m][q*2] = make_uint2(l0, l1);
        }
        // ---- fill B tile (direct copy, packed [kpair][n]) ----
        {
            int kpr = tid >> 4, q = tid & 15;
            long src = (long)(kt*16 + kpr)*256 + bn;
            *(uint4*)&BsH[kpr][q*4] = ((const uint4*)(WH + src))[q];
            *(uint4*)&BsL[kpr][q*4] = ((const uint4*)(WL + src))[q];
        }
        __syncthreads();
#pragma unroll
        for (int ks = 0; ks < 2; ks++) {
            int kpb = ks * 8;
            unsigned aH0 = AsH[wm+ld4  ][kpb+lp4  ];
            unsigned aH1 = AsH[wm+ld4+8][kpb+lp4  ];
            unsigned aH2 = AsH[wm+ld4  ][kpb+lp4+4];
            unsigned aH3 = AsH[wm+ld4+8][kpb+lp4+4];
            unsigned aL0 = AsL[wm+ld4  ][kpb+lp4  ];
            unsigned aL1 = AsL[wm+ld4+8][kpb+lp4  ];
            unsigned aL2 = AsL[wm+ld4  ][kpb+lp4+4];
            unsigned aL3 = AsL[wm+ld4+8][kpb+lp4+4];
#pragma unroll
            for (int nf = 0; nf < 4; nf++) {
                int col = wn + nf*8 + ld4;
                unsigned bH0 = BsH[kpb+lp4  ][col];
                unsigned bH1 = BsH[kpb+lp4+4][col];
                unsigned bL0 = BsL[kpb+lp4  ][col];
                unsigned bL1 = BsL[kpb+lp4+4][col];
                mma_bf16(acc[nf][0], acc[nf][1], acc[nf][2], acc[nf][3],
                         aH0, aH1, aH2, aH3, bH0, bH1);
                mma_bf16(acc[nf][0], acc[nf][1], acc[nf][2], acc[nf][3],
                         aL0, aL1, aL2, aL3, bH0, bH1);
                mma_bf16(acc[nf][0], acc[nf][1], acc[nf][2], acc[nf][3],
                         aH0, aH1, aH2, aH3, bL0, bL1);
            }
        }
        __syncthreads();
    }

    // ---- epilogue ----
    int r0 = bm + wm + ld4, r1 = r0 + 8;
#pragma unroll
    for (int nf = 0; nf < 4; nf++) {
        int n = bn + wn + nf*8 + lp4*2;
        float b0v = __ldg(bias + n), b1v = __ldg(bias + n + 1);
        if (r0 < M) {
            float2 o = make_float2(acc[nf][0] + b0v, acc[nf][1] + b1v);
            if (omask && omask[r0] != 0) o = make_float2(0.f, 0.f);
            *(float2*)(C + (long)r0*256 + n) = o;
        }
        if (r1 < M) {
            float2 o = make_float2(acc[nf][2] + b0v, acc[nf][3] + b1v);
            if (omask && omask[r1] != 0) o = make_float2(0.f, 0.f);
            *(float2*)(C + (long)r1*256 + n) = o;
        }
    }
}

// ---------------- K3: bilinear sampling over 4 levels (compacted) ------------
__constant__ int c_H[4] = {112, 56, 28, 14};
__constant__ int c_W[4] = {200, 100, 50, 25};

__global__ __launch_bounds__(128) void sample_kernel(
    const float* __restrict__ f0, const float* __restrict__ f1,
    const float* __restrict__ f2, const float* __restrict__ f3)
{
    int cnt = g_count;
    const float* fp[4] = {f0, f1, f2, f3};
    for (int i = blockIdx.x; i < cnt; i += gridDim.x) {
        float4 pc = g_projc[i];
        float X = pc.x, Y = pc.y;
        int cam = (int)pc.z;

        int   off[4][4];
        float wei[4][4];
#pragma unroll
        for (int l = 0; l < 4; l++) {
            int H = c_H[l], W = c_W[l];
            float fx = X * ((float)W / 800.0f);
            float fy = Y * ((float)H / 448.0f);
            float gx = fminf(fmaxf(fx / (float)(W-1) * 2.0f - 1.0f, -10.f), 10.f);
            float gy = fminf(fmaxf(fy / (float)(H-1) * 2.0f - 1.0f, -10.f), 10.f);
            float px = (gx + 1.0f) * 0.5f * (float)(W-1);
            float py = (gy + 1.0f) * 0.5f * (float)(H-1);
            float x0f = floorf(px), y0f = floorf(py);
            int x0 = (int)x0f, y0 = (int)y0f;
            float wx = px - x0f, wy = py - y0f;
            bool vx0 = (x0 >= 0)   && (x0 < W);
            bool vx1 = (x0+1 >= 0) && (x0+1 < W);
            bool vy0 = (y0 >= 0)   && (y0 < H);
            bool vy1 = (y0+1 >= 0) && (y0+1 < H);
            int xc0 = min(max(x0, 0), W-1),  xc1 = min(max(x0+1, 0), W-1);
            int yc0 = min(max(y0, 0), H-1),  yc1 = min(max(y0+1, 0), H-1);
            off[l][0] = (vy0 && vx0) ? yc0*W + xc0 : -1;
            off[l][1] = (vy0 && vx1) ? yc0*W + xc1 : -1;
            off[l][2] = (vy1 && vx0) ? yc1*W + xc0 : -1;
            off[l][3] = (vy1 && vx1) ? yc1*W + xc1 : -1;
            wei[l][0] = (1.f-wx)*(1.f-wy);
            wei[l][1] = wx*(1.f-wy);
            wei[l][2] = (1.f-wx)*wy;
            wei[l][3] = wx*wy;
        }
#pragma unroll
        for (int cc = 0; cc < 2; cc++) {
            int c = threadIdx.x + cc*128;
            float acc = 0.f;
#pragma unroll
            for (int l = 0; l < 4; l++) {
                int HW = c_H[l] * c_W[l];
                const float* base = fp[l] + (long)(cam*Cn + c) * HW;
#pragma unroll
                for (int r = 0; r < 4; r++) {
                    int o = off[l][r];
                    if (o >= 0) acc += __ldg(base + o) * wei[l][r];
                }
            }
            g_ms[(long)i*Cn + c] = acc * 0.25f;
        }
    }
}

// ---------------- K5: max over cameras + fuse --------------------------------
__global__ void maxfuse_kernel(const float* __restrict__ bv) {
    int bq = blockIdx.x;
    int c = threadIdx.x;
    int b = bq / Qn, q = bq % Qn;
    __shared__ int slots[Ncam];
    if (c < Ncam) slots[c] = g_map[(b*Ncam + c)*Qn + q];
    __syncthreads();
    float bvv = __ldg(bv + c);
    float m = -FLT_MAX;
#pragma unroll
    for (int n = 0; n < Ncam; n++) {
        int s = slots[n];
        float v = (s >= 0) ? g_v[(long)s*Cn + c] : bvv;
        m = fmaxf(m, v);
    }
    float qv = g_q[(long)bq*Cn + c];
    g_fu[(long)bq*Cn + c] = fmaxf(qv + m, 0.f) + qv;
}

// ---------------- launch ------------------------------------------------------
extern "C" void kernel_launch(void* const* d_in, const int* in_sizes, int n_in,
                              void* d_out, int out_size) {
    const float* query  = (const float*)d_in[0];
    const float* refpts = (const float*)d_in[1];
    const int*   mask   = (const int*)  d_in[2];
    const float* intr   = (const float*)d_in[3];
    const float* ext    = (const float*)d_in[4];
    const float* f0     = (const float*)d_in[5];
    const float* f1     = (const float*)d_in[6];
    const float* f2     = (const float*)d_in[7];
    const float* f3     = (const float*)d_in[8];
    const float* Wq     = (const float*)d_in[9];
    const float* bq     = (const float*)d_in[10];
    const float* Wv     = (const float*)d_in[11];
    const float* bv     = (const float*)d_in[12];
    const float* Wo     = (const float*)d_in[13];
    const float* bo     = (const float*)d_in[14];

    float *p_ms, *p_v, *p_q, *p_fu;
    cudaGetSymbolAddress((void**)&p_ms, g_ms);
    cudaGetSymbolAddress((void**)&p_v,  g_v);
    cudaGetSymbolAddress((void**)&p_q,  g_q);
    cudaGetSymbolAddress((void**)&p_fu, g_fu);

    invert_kernel<<<1, 32>>>(ext);
    prep_weights<<<384, 256>>>(Wq, Wv, Wo);
    project_kernel<<<(NP + 127)/128, 128>>>(refpts, mask, intr);

    // q = query @ Wq^T + bq
    tgemm_kernel<<<dim3(4, (BQ + 63)/64), 256>>>(query, 0, bq, p_q, BQ, 0, nullptr);

    sample_kernel<<<888, 128>>>(f0, f1, f2, f3);

    // v = ms @ Wv^T + bv (dynamic M = g_count)
    tgemm_kernel<<<dim3(4, (NP + 63)/64), 256>>>(p_ms, 1, bv, p_v, NP, 1, nullptr);

    maxfuse_kernel<<<BQ, Cn>>>(bv);

    // out = fused @ Wo^T + bo, masked rows -> 0
    tgemm_kernel<<<dim3(4, (BQ + 63)/64), 256>>>(p_fu, 2, bo, (float*)d_out, BQ, 0, mask);
}

// round 7
// speedup vs baseline: 1.4503x; 1.0931x over previous
#include <cuda_runtime.h>
#include <cuda_bf16.h>
#include <math.h>
#include <float.h>

#define Bb   2
#define Qn   900
#define Cn   256
#define Ncam 6
#define NP   (Bb*Ncam*Qn)   // 10800
#define BQ   (Bb*Qn)        // 1800

// ---------------- scratch (static device globals; no allocation) -------------
__device__ float  g_inv[Bb*Ncam*16];
__device__ int    g_count;
__device__ int    g_map[NP];
__device__ float4 g_projc[NP];
__device__ float  g_v [NP*Cn];
__device__ float  g_q [BQ*Cn];
// packed split-bf16 operands: word (row,kp) packs bf16(x[2kp]),bf16(x[2kp+1])
__device__ unsigned g_WH[3][128*256], g_WL[3][128*256];   // weights [kpair][n]
__device__ unsigned g_aqH[BQ*128],  g_aqL[BQ*128];        // query   [m][kpair]
__device__ unsigned g_msH[NP*128],  g_msL[NP*128];        // sampled [m][kpair]
__device__ unsigned g_fuH[BQ*128],  g_fuL[BQ*128];        // fused   [m][kpair]

// ---------------- helpers ----------------------------------------------------
__device__ __forceinline__ void split2(float a, float b, unsigned& h, unsigned& l) {
    __nv_bfloat16 ah = __float2bfloat16(a), bh = __float2bfloat16(b);
    __nv_bfloat16 al = __float2bfloat16(a - __bfloat162float(ah));
    __nv_bfloat16 bl = __float2bfloat16(b - __bfloat162float(bh));
    h = (unsigned)__bfloat16_as_ushort(ah) | ((unsigned)__bfloat16_as_ushort(bh) << 16);
    l = (unsigned)__bfloat16_as_ushort(al) | ((unsigned)__bfloat16_as_ushort(bl) << 16);
}

__device__ __forceinline__ void cpa16(void* dst_smem, const void* src) {
    unsigned d = (unsigned)__cvta_generic_to_shared(dst_smem);
    asm volatile("cp.async.cg.shared.global [%0], [%1], 16;" :: "r"(d), "l"(src));
}
__device__ __forceinline__ void cpa_commit() { asm volatile("cp.async.commit_group;"); }
template<int N> __device__ __forceinline__ void cpa_wait() {
    asm volatile("cp.async.wait_group %0;" :: "n"(N));
}

__device__ __forceinline__ void mma_bf16(float& d0, float& d1, float& d2, float& d3,
    unsigned a0, unsigned a1, unsigned a2, unsigned a3, unsigned b0, unsigned b1) {
    asm volatile("mma.sync.aligned.m16n8k16.row.col.f32.bf16.bf16.f32 "
        "{%0,%1,%2,%3}, {%4,%5,%6,%7}, {%8,%9}, {%0,%1,%2,%3};"
        : "+f"(d0), "+f"(d1), "+f"(d2), "+f"(d3)
        : "r"(a0), "r"(a1), "r"(a2), "r"(a3), "r"(b0), "r"(b1));
}

// ---------------- K1: batched 4x4 inverse ------------------------------------
__global__ void invert_kernel(const float* __restrict__ ext) {
    int t = threadIdx.x;
    if (t == 0) g_count = 0;
    if (t >= Bb*Ncam) return;
    const float* E = ext + t*16;
    double a[4][8];
    for (int i = 0; i < 4; i++)
        for (int j = 0; j < 4; j++) { a[i][j] = (double)E[i*4+j]; a[i][4+j] = (i==j) ? 1.0 : 0.0; }
    for (int c = 0; c < 4; c++) {
        int p = c; double mv = fabs(a[c][c]);
        for (int r = c+1; r < 4; r++) { double v = fabs(a[r][c]); if (v > mv) { mv = v; p = r; } }
        if (p != c) for (int j = 0; j < 8; j++) { double tmp = a[c][j]; a[c][j] = a[p][j]; a[p][j] = tmp; }
        double ip = 1.0 / a[c][c];
        for (int j = 0; j < 8; j++) a[c][j] *= ip;
        for (int r = 0; r < 4; r++) if (r != c) {
            double f = a[r][c];
            for (int j = 0; j < 8; j++) a[r][j] -= f * a[c][j];
        }
    }
    for (int i = 0; i < 4; i++)
        for (int j = 0; j < 4; j++) {
            float f = (float)a[i][4+j];
            if (isnan(f)) f = 0.0f;
            else if (isinf(f)) f = (f > 0.f) ? 1e6f : -1e6f;
            g_inv[t*16 + i*4 + j] = f;
        }
}

// ---------------- prep: pack weights + query ---------------------------------
#define PREP_W (3*128*256)
#define PREP_Q (BQ*128)
__global__ void prep_kernel(const float* __restrict__ Wq, const float* __restrict__ Wv,
                            const float* __restrict__ Wo, const float* __restrict__ query) {
    int idx = blockIdx.x * blockDim.x + threadIdx.x;
    if (idx < PREP_W) {
        int w   = idx / (128*256);
        int rem = idx % (128*256);
        int kp  = rem / 256;
        int n   = rem % 256;
        const float* W = (w==0) ? Wq : ((w==1) ? Wv : Wo);
        unsigned h, l;
        split2(W[n*256 + kp*2], W[n*256 + kp*2 + 1], h, l);
        g_WH[w][rem] = h; g_WL[w][rem] = l;
    } else if (idx < PREP_W + PREP_Q) {
        int j = idx - PREP_W;
        int m = j >> 7, kp = j & 127;
        unsigned h, l;
        split2(query[m*256 + kp*2], query[m*256 + kp*2 + 1], h, l);
        g_aqH[j] = h; g_aqL[j] = l;
    }
}

// ---------------- K2: project + candidate compaction -------------------------
__global__ void project_kernel(const float* __restrict__ refpts,
                               const int*   __restrict__ mask,
                               const float* __restrict__ intr) {
    int p = blockIdx.x * blockDim.x + threadIdx.x;
    if (p >= NP) return;
    int b = p / (Ncam*Qn);
    int n = (p / Qn) % Ncam;
    int q = p % Qn;
    int bq = b*Qn + q;
    if (mask[bq] != 0) { g_map[p] = -1; return; }

    float r0 = refpts[bq*3+0] * 102.4f - 51.2f;
    float r1 = refpts[bq*3+1] * 102.4f - 51.2f;
    float r2 = refpts[bq*3+2] * 102.4f - 51.2f;

    const float* iv = g_inv + (b*Ncam + n)*16;
    float p0 = iv[0]*r0 + iv[1]*r1 + iv[2]*r2  + iv[3];
    float p1 = iv[4]*r0 + iv[5]*r1 + iv[6]*r2  + iv[7];
    float p2 = iv[8]*r0 + iv[9]*r1 + iv[10]*r2 + iv[11];

    float depth = p2;
    if (isnan(depth)) depth = 10.0f;
    else if (isinf(depth)) depth = (depth > 0.f) ? 100.0f : -100.0f;
    bool invalid = depth < 1.5f;
    float ds = fmaxf(depth, 1.5f);

    float cx = p0 / ds, cy = p1 / ds, cz = p2 / ds;
    const float* Km = intr + (b*Ncam + n)*9;
    float ix = Km[0]*cx + Km[1]*cy + Km[2]*cz;
    float iy = Km[3]*cx + Km[4]*cy + Km[5]*cz;
    ix = fminf(fmaxf(ix, -3000.f), 3000.f);
    iy = fminf(fmaxf(iy, -3000.f), 3000.f);

    bool cand = !invalid && (ix >= -32.f) && (ix < 800.f) && (iy >= -32.f) && (iy < 448.f);
    int slot = -1;
    if (cand) {
        slot = atomicAdd(&g_count, 1);
        g_projc[slot] = make_float4(ix, iy, (float)(b*Ncam + n), 0.f);
    }
    g_map[p] = slot;
}

// ---------------- pipelined tensor-core GEMM core ----------------------------
// C[M,256] = unpack(AH,AL) @ unpack(W)^T + bias.  BM=64,BN=64,BK=32, 256 thr.
// A packed [m][128 kpair], W packed [kpair][256]. 2-stage cp.async pipeline.
struct GemmSmem {
    unsigned AsH[2][64][20], AsL[2][64][20];
    unsigned BsH[2][16][72], BsL[2][16][72];
};

__device__ __forceinline__ void gemm_load_stage(
    GemmSmem& S, int s, int kt,
    const unsigned* __restrict__ AH, const unsigned* __restrict__ AL,
    const unsigned* __restrict__ WH, const unsigned* __restrict__ WL,
    int bm, int bn, int M)
{
    int tid = threadIdx.x;
    // A: 256 chunks of 16B each for H and L
    {
        int m = tid >> 2, q = tid & 3;
        int row = min(bm + m, M-1);
        long src = (long)row*128 + kt*16 + q*4;
        cpa16(&S.AsH[s][m][q*4], AH + src);
        cpa16(&S.AsL[s][m][q*4], AL + src);
    }
    // B: 256 chunks for H, 256 for L
    {
        int kpr = tid >> 4, q = tid & 15;
        long src = (long)(kt*16 + kpr)*256 + bn + q*4;
        cpa16(&S.BsH[s][kpr][q*4], WH + src);
        cpa16(&S.BsL[s][kpr][q*4], WL + src);
    }
    cpa_commit();
}

__device__ __forceinline__ void gemm_core(
    GemmSmem& S,
    const unsigned* __restrict__ AH, const unsigned* __restrict__ AL,
    const unsigned* __restrict__ WH, const unsigned* __restrict__ WL,
    const float* __restrict__ bias, float* __restrict__ C,
    int M, int bm, int bn, const int* __restrict__ omask)
{
    int tid  = threadIdx.x;
    int lane = tid & 31, warp = tid >> 5;
    int wm = (warp & 3) * 16, wn = (warp >> 2) * 32;
    int ld4 = lane >> 2, lp4 = lane & 3;

    float acc[4][4];
#pragma unroll
    for (int i = 0; i < 4; i++)
#pragma unroll
        for (int j = 0; j < 4; j++) acc[i][j] = 0.f;

    gemm_load_stage(S, 0, 0, AH, AL, WH, WL, bm, bn, M);

    for (int kt = 0; kt < 8; kt++) {
        int s = kt & 1;
        if (kt < 7) {
            gemm_load_stage(S, s ^ 1, kt + 1, AH, AL, WH, WL, bm, bn, M);
            cpa_wait<1>();
        } else {
            cpa_wait<0>();
        }
        __syncthreads();
#pragma unroll
        for (int ks = 0; ks < 2; ks++) {
            int kpb = ks * 8;
            unsigned aH0 = S.AsH[s][wm+ld4  ][kpb+lp4  ];
            unsigned aH1 = S.AsH[s][wm+ld4+8][kpb+lp4  ];
            unsigned aH2 = S.AsH[s][wm+ld4  ][kpb+lp4+4];
            unsigned aH3 = S.AsH[s][wm+ld4+8][kpb+lp4+4];
            unsigned aL0 = S.AsL[s][wm+ld4  ][kpb+lp4  ];
            unsigned aL1 = S.AsL[s][wm+ld4+8][kpb+lp4  ];
            unsigned aL2 = S.AsL[s][wm+ld4  ][kpb+lp4+4];
            unsigned aL3 = S.AsL[s][wm+ld4+8][kpb+lp4+4];
#pragma unroll
            for (int nf = 0; nf < 4; nf++) {
                int col = wn + nf*8 + ld4;
                unsigned bH0 = S.BsH[s][kpb+lp4  ][col];
                unsigned bH1 = S.BsH[s][kpb+lp4+4][col];
                unsigned bL0 = S.BsL[s][kpb+lp4  ][col];
                unsigned bL1 = S.BsL[s][kpb+lp4+4][col];
                mma_bf16(acc[nf][0], acc[nf][1], acc[nf][2], acc[nf][3],
                         aH0, aH1, aH2, aH3, bH0, bH1);
                mma_bf16(acc[nf][0], acc[nf][1], acc[nf][2], acc[nf][3],
                         aL0, aL1, aL2, aL3, bH0, bH1);
                mma_bf16(acc[nf][0], acc[nf][1], acc[nf][2], acc[nf][3],
                         aH0, aH1, aH2, aH3, bL0, bL1);
            }
        }
        __syncthreads();
    }

    int r0 = bm + wm + ld4, r1 = r0 + 8;
#pragma unroll
    for (int nf = 0; nf < 4; nf++) {
        int n = bn + wn + nf*8 + lp4*2;
        float b0v = __ldg(bias + n), b1v = __ldg(bias + n + 1);
        if (r0 < M) {
            float2 o = make_float2(acc[nf][0] + b0v, acc[nf][1] + b1v);
            if (omask && omask[r0] != 0) o = make_float2(0.f, 0.f);
            *(float2*)(C + (long)r0*256 + n) = o;
        }
        if (r1 < M) {
            float2 o = make_float2(acc[nf][2] + b0v, acc[nf][3] + b1v);
            if (omask && omask[r1] != 0) o = make_float2(0.f, 0.f);
            *(float2*)(C + (long)r1*256 + n) = o;
        }
    }
}

// ---------------- fused: q-GEMM blocks + sampling blocks ---------------------
#define GQ_BLOCKS  (((BQ + 63)/64) * 4)      // 29*4 = 116
#define SAMP_BLOCKS 772

__constant__ int c_H[4] = {112, 56, 28, 14};
__constant__ int c_W[4] = {200, 100, 50, 25};

__global__ __launch_bounds__(256) void fused_qsample_kernel(
    const float* __restrict__ bq,
    const float* __restrict__ f0, const float* __restrict__ f1,
    const float* __restrict__ f2, const float* __restrict__ f3)
{
    __shared__ GemmSmem S;
    int bid = blockIdx.x;
    if (bid < GQ_BLOCKS) {
        int bm = (bid >> 2) * 64;
        int bn = (bid & 3) * 64;
        gemm_core(S, g_aqH, g_aqL, g_WH[0], g_WL[0], bq, g_q, BQ, bm, bn, nullptr);
        return;
    }
    // -------- sampling: one point per block-iteration, 256 threads=channels --
    int cnt = g_count;
    const float* fp[4] = {f0, f1, f2, f3};
    int t = threadIdx.x;
    for (int i = bid - GQ_BLOCKS; i < cnt; i += SAMP_BLOCKS) {
        float4 pc = g_projc[i];
        float X = pc.x, Y = pc.y;
        int cam = (int)pc.z;

        int   off[4][4];
        float wei[4][4];
#pragma unroll
        for (int l = 0; l < 4; l++) {
            int H = c_H[l], W = c_W[l];
            float fx = X * ((float)W / 800.0f);
            float fy = Y * ((float)H / 448.0f);
            float gx = fminf(fmaxf(fx / (float)(W-1) * 2.0f - 1.0f, -10.f), 10.f);
            float gy = fminf(fmaxf(fy / (float)(H-1) * 2.0f - 1.0f, -10.f), 10.f);
            float px = (gx + 1.0f) * 0.5f * (float)(W-1);
            float py = (gy + 1.0f) * 0.5f * (float)(H-1);
            float x0f = floorf(px), y0f = floorf(py);
            int x0 = (int)x0f, y0 = (int)y0f;
            float wx = px - x0f, wy = py - y0f;
            bool vx0 = (x0 >= 0)   && (x0 < W);
            bool vx1 = (x0+1 >= 0) && (x0+1 < W);
            bool vy0 = (y0 >= 0)   && (y0 < H);
            bool vy1 = (y0+1 >= 0) && (y0+1 < H);
            int xc0 = min(max(x0, 0), W-1),  xc1 = min(max(x0+1, 0), W-1);
            int yc0 = min(max(y0, 0), H-1),  yc1 = min(max(y0+1, 0), H-1);
            off[l][0] = (vy0 && vx0) ? yc0*W + xc0 : -1;
            off[l][1] = (vy0 && vx1) ? yc0*W + xc1 : -1;
            off[l][2] = (vy1 && vx0) ? yc1*W + xc0 : -1;
            off[l][3] = (vy1 && vx1) ? yc1*W + xc1 : -1;
            wei[l][0] = (1.f-wx)*(1.f-wy);
            wei[l][1] = wx*(1.f-wy);
            wei[l][2] = (1.f-wx)*wy;
            wei[l][3] = wx*wy;
        }
        float acc = 0.f;
#pragma unroll
        for (int l = 0; l < 4; l++) {
            int HW = c_H[l] * c_W[l];
            const float* base = fp[l] + (long)(cam*Cn + t) * HW;
#pragma unroll
            for (int r = 0; r < 4; r++) {
                int o = off[l][r];
                if (o >= 0) acc += __ldg(base + o) * wei[l][r];
            }
        }
        float val = acc * 0.25f;
        float other = __shfl_xor_sync(0xffffffffu, val, 1);
        if ((t & 1) == 0) {
            unsigned h, l;
            split2(val, other, h, l);
            g_msH[(long)i*128 + (t >> 1)] = h;
            g_msL[(long)i*128 + (t >> 1)] = l;
        }
    }
}

// ---------------- v-GEMM (dynamic M) -----------------------------------------
__global__ __launch_bounds__(256) void vgemm_kernel(const float* __restrict__ bv) {
    __shared__ GemmSmem S;
    int M = g_count;
    int bm = blockIdx.y * 64;
    if (bm >= M) return;
    int bn = blockIdx.x * 64;
    gemm_core(S, g_msH, g_msL, g_WH[1], g_WL[1], bv, g_v, M, bm, bn, nullptr);
}

// ---------------- maxfuse: max over cams + relu-fuse + pack ------------------
__global__ void maxfuse_kernel(const float* __restrict__ bv) {
    int bq = blockIdx.x;
    int t = threadIdx.x;          // 128 threads, channels 2t,2t+1
    int b = bq / Qn, q = bq % Qn;
    __shared__ int slots[Ncam];
    if (t < Ncam) slots[t] = g_map[(b*Ncam + t)*Qn + q];
    __syncthreads();
    int c0 = 2*t, c1 = 2*t + 1;
    float bv0 = __ldg(bv + c0), bv1 = __ldg(bv + c1);
    float m0 = -FLT_MAX, m1 = -FLT_MAX;
#pragma unroll
    for (int n = 0; n < Ncam; n++) {
        int s = slots[n];
        float v0 = (s >= 0) ? g_v[(long)s*Cn + c0] : bv0;
        float v1 = (s >= 0) ? g_v[(long)s*Cn + c1] : bv1;
        m0 = fmaxf(m0, v0);
        m1 = fmaxf(m1, v1);
    }
    float q0 = g_q[(long)bq*Cn + c0], q1 = g_q[(long)bq*Cn + c1];
    float f0 = fmaxf(q0 + m0, 0.f) + q0;
    float f1 = fmaxf(q1 + m1, 0.f) + q1;
    unsigned h, l;
    split2(f0, f1, h, l);
    g_fuH[(long)bq*128 + t] = h;
    g_fuL[(long)bq*128 + t] = l;
}

// ---------------- o-GEMM -----------------------------------------------------
__global__ __launch_bounds__(256) void ogemm_kernel(
    const float* __restrict__ bo, float* __restrict__ out,
    const int* __restrict__ mask)
{
    __shared__ GemmSmem S;
    int bm = blockIdx.y * 64;
    int bn = blockIdx.x * 64;
    gemm_core(S, g_fuH, g_fuL, g_WH[2], g_WL[2], bo, out, BQ, bm, bn, mask);
}

// ---------------- launch ------------------------------------------------------
extern "C" void kernel_launch(void* const* d_in, const int* in_sizes, int n_in,
                              void* d_out, int out_size) {
    const float* query  = (const float*)d_in[0];
    const float* refpts = (const float*)d_in[1];
    const int*   mask   = (const int*)  d_in[2];
    const float* intr   = (const float*)d_in[3];
    const float* ext    = (const float*)d_in[4];
    const float* f0     = (const float*)d_in[5];
    const float* f1     = (const float*)d_in[6];
    const float* f2     = (const float*)d_in[7];
    const float* f3     = (const float*)d_in[8];
    const float* bq     = (const float*)d_in[10];
    const float* Wq     = (const float*)d_in[9];
    const float* Wv     = (const float*)d_in[11];
    const float* bv     = (const float*)d_in[12];
    const float* Wo     = (const float*)d_in[13];
    const float* bo     = (const float*)d_in[14];

    invert_kernel<<<1, 32>>>(ext);
    prep_kernel<<<(PREP_W + PREP_Q + 255)/256, 256>>>(Wq, Wv, Wo, query);
    project_kernel<<<(NP + 127)/128, 128>>>(refpts, mask, intr);
    fused_qsample_kernel<<<GQ_BLOCKS + SAMP_BLOCKS, 256>>>(bq, f0, f1, f2, f3);
    vgemm_kernel<<<dim3(4, (NP + 63)/64), 256>>>(bv);
    maxfuse_kernel<<<BQ, 128>>>(bv);
    ogemm_kernel<<<dim3(4, (BQ + 63)/64), 256>>>(bo, (float*)d_out, mask);
}

// round 8
// speedup vs baseline: 1.5152x; 1.0447x over previous
#include <cuda_runtime.h>
#include <cuda_bf16.h>
#include <math.h>
#include <float.h>

#define Bb   2
#define Qn   900
#define Cn   256
#define Ncam 6
#define NP   (Bb*Ncam*Qn)   // 10800
#define BQ   (Bb*Qn)        // 1800

// ---------------- scratch (static device globals; no allocation) -------------
__device__ float  g_inv[Bb*Ncam*16];
__device__ int    g_count;
__device__ int    g_map[NP];
__device__ float4 g_projc[NP];
__device__ float  g_v [NP*Cn];
__device__ float  g_q [BQ*Cn];
// packed split-bf16 operands: word (row,kp) packs bf16(x[2kp]),bf16(x[2kp+1])
__device__ unsigned g_WH[3][128*256], g_WL[3][128*256];   // weights [kpair][n]
__device__ unsigned g_aqH[BQ*128],  g_aqL[BQ*128];        // query   [m][kpair]
__device__ unsigned g_msH[NP*128],  g_msL[NP*128];        // sampled [m][kpair]
__device__ unsigned g_fuH[BQ*128],  g_fuL[BQ*128];        // fused   [m][kpair]

// ---------------- helpers ----------------------------------------------------
__device__ __forceinline__ void split2(float a, float b, unsigned& h, unsigned& l) {
    __nv_bfloat16 ah = __float2bfloat16(a), bh = __float2bfloat16(b);
    __nv_bfloat16 al = __float2bfloat16(a - __bfloat162float(ah));
    __nv_bfloat16 bl = __float2bfloat16(b - __bfloat162float(bh));
    h = (unsigned)__bfloat16_as_ushort(ah) | ((unsigned)__bfloat16_as_ushort(bh) << 16);
    l = (unsigned)__bfloat16_as_ushort(al) | ((unsigned)__bfloat16_as_ushort(bl) << 16);
}

__device__ __forceinline__ void cpa16(void* dst_smem, const void* src) {
    unsigned d = (unsigned)__cvta_generic_to_shared(dst_smem);
    asm volatile("cp.async.cg.shared.global [%0], [%1], 16;" :: "r"(d), "l"(src));
}
__device__ __forceinline__ void cpa_commit() { asm volatile("cp.async.commit_group;"); }
template<int N> __device__ __forceinline__ void cpa_wait() {
    asm volatile("cp.async.wait_group %0;" :: "n"(N));
}

__device__ __forceinline__ void mma_bf16(float& d0, float& d1, float& d2, float& d3,
    unsigned a0, unsigned a1, unsigned a2, unsigned a3, unsigned b0, unsigned b1) {
    asm volatile("mma.sync.aligned.m16n8k16.row.col.f32.bf16.bf16.f32 "
        "{%0,%1,%2,%3}, {%4,%5,%6,%7}, {%8,%9}, {%0,%1,%2,%3};"
        : "+f"(d0), "+f"(d1), "+f"(d2), "+f"(d3)
        : "r"(a0), "r"(a1), "r"(a2), "r"(a3), "r"(b0), "r"(b1));
}

// ---------------- K1: batched 4x4 inverse ------------------------------------
__global__ void invert_kernel(const float* __restrict__ ext) {
    int t = threadIdx.x;
    if (t == 0) g_count = 0;
    if (t >= Bb*Ncam) return;
    const float* E = ext + t*16;
    double a[4][8];
    for (int i = 0; i < 4; i++)
        for (int j = 0; j < 4; j++) { a[i][j] = (double)E[i*4+j]; a[i][4+j] = (i==j) ? 1.0 : 0.0; }
    for (int c = 0; c < 4; c++) {
        int p = c; double mv = fabs(a[c][c]);
        for (int r = c+1; r < 4; r++) { double v = fabs(a[r][c]); if (v > mv) { mv = v; p = r; } }
        if (p != c) for (int j = 0; j < 8; j++) { double tmp = a[c][j]; a[c][j] = a[p][j]; a[p][j] = tmp; }
        double ip = 1.0 / a[c][c];
        for (int j = 0; j < 8; j++) a[c][j] *= ip;
        for (int r = 0; r < 4; r++) if (r != c) {
            double f = a[r][c];
            for (int j = 0; j < 8; j++) a[r][j] -= f * a[c][j];
        }
    }
    for (int i = 0; i < 4; i++)
        for (int j = 0; j < 4; j++) {
            float f = (float)a[i][4+j];
            if (isnan(f)) f = 0.0f;
            else if (isinf(f)) f = (f > 0.f) ? 1e6f : -1e6f;
            g_inv[t*16 + i*4 + j] = f;
        }
}

// ---------------- prep: pack weights + query ---------------------------------
#define PREP_W (3*128*256)
#define PREP_Q (BQ*128)
__global__ void prep_kernel(const float* __restrict__ Wq, const float* __restrict__ Wv,
                            const float* __restrict__ Wo, const float* __restrict__ query) {
    int idx = blockIdx.x * blockDim.x + threadIdx.x;
    if (idx < PREP_W) {
        int w   = idx / (128*256);
        int rem = idx % (128*256);
        int kp  = rem / 256;
        int n   = rem % 256;
        const float* W = (w==0) ? Wq : ((w==1) ? Wv : Wo);
        unsigned h, l;
        split2(W[n*256 + kp*2], W[n*256 + kp*2 + 1], h, l);
        g_WH[w][rem] = h; g_WL[w][rem] = l;
    } else if (idx < PREP_W + PREP_Q) {
        int j = idx - PREP_W;
        int m = j >> 7, kp = j & 127;
        unsigned h, l;
        split2(query[m*256 + kp*2], query[m*256 + kp*2 + 1], h, l);
        g_aqH[j] = h; g_aqL[j] = l;
    }
}

// ---------------- K2: project + candidate compaction -------------------------
__global__ void project_kernel(const float* __restrict__ refpts,
                               const int*   __restrict__ mask,
                               const float* __restrict__ intr) {
    int p = blockIdx.x * blockDim.x + threadIdx.x;
    if (p >= NP) return;
    int b = p / (Ncam*Qn);
    int n = (p / Qn) % Ncam;
    int q = p % Qn;
    int bq = b*Qn + q;
    if (mask[bq] != 0) { g_map[p] = -1; return; }

    float r0 = refpts[bq*3+0] * 102.4f - 51.2f;
    float r1 = refpts[bq*3+1] * 102.4f - 51.2f;
    float r2 = refpts[bq*3+2] * 102.4f - 51.2f;

    const float* iv = g_inv + (b*Ncam + n)*16;
    float p0 = iv[0]*r0 + iv[1]*r1 + iv[2]*r2  + iv[3];
    float p1 = iv[4]*r0 + iv[5]*r1 + iv[6]*r2  + iv[7];
    float p2 = iv[8]*r0 + iv[9]*r1 + iv[10]*r2 + iv[11];

    float depth = p2;
    if (isnan(depth)) depth = 10.0f;
    else if (isinf(depth)) depth = (depth > 0.f) ? 100.0f : -100.0f;
    bool invalid = depth < 1.5f;
    float ds = fmaxf(depth, 1.5f);

    float cx = p0 / ds, cy = p1 / ds, cz = p2 / ds;
    const float* Km = intr + (b*Ncam + n)*9;
    float ix = Km[0]*cx + Km[1]*cy + Km[2]*cz;
    float iy = Km[3]*cx + Km[4]*cy + Km[5]*cz;
    ix = fminf(fmaxf(ix, -3000.f), 3000.f);
    iy = fminf(fmaxf(iy, -3000.f), 3000.f);

    bool cand = !invalid && (ix >= -32.f) && (ix < 800.f) && (iy >= -32.f) && (iy < 448.f);
    int slot = -1;
    if (cand) {
        slot = atomicAdd(&g_count, 1);
        g_projc[slot] = make_float4(ix, iy, (float)(b*Ncam + n), 0.f);
    }
    g_map[p] = slot;
}

// ---------------- pipelined tensor-core GEMM core ----------------------------
// C[M,256] = unpack(AH,AL) @ unpack(W)^T + bias.  BM=64,BN=64,BK=32, 256 thr.
// A packed [m][128 kpair], W packed [kpair][256]. 2-stage cp.async pipeline.
struct GemmSmem {
    unsigned AsH[2][64][20], AsL[2][64][20];
    unsigned BsH[2][16][72], BsL[2][16][72];
};

__device__ __forceinline__ void gemm_load_stage(
    GemmSmem& S, int s, int kt,
    const unsigned* __restrict__ AH, const unsigned* __restrict__ AL,
    const unsigned* __restrict__ WH, const unsigned* __restrict__ WL,
    int bm, int bn, int M)
{
    int tid = threadIdx.x;
    // A: 256 chunks of 16B each for H and L
    {
        int m = tid >> 2, q = tid & 3;
        int row = min(bm + m, M-1);
        long src = (long)row*128 + kt*16 + q*4;
        cpa16(&S.AsH[s][m][q*4], AH + src);
        cpa16(&S.AsL[s][m][q*4], AL + src);
    }
    // B: 256 chunks for H, 256 for L
    {
        int kpr = tid >> 4, q = tid & 15;
        long src = (long)(kt*16 + kpr)*256 + bn + q*4;
        cpa16(&S.BsH[s][kpr][q*4], WH + src);
        cpa16(&S.BsL[s][kpr][q*4], WL + src);
    }
    cpa_commit();
}

__device__ __forceinline__ void gemm_core(
    GemmSmem& S,
    const unsigned* __restrict__ AH, const unsigned* __restrict__ AL,
    const unsigned* __restrict__ WH, const unsigned* __restrict__ WL,
    const float* __restrict__ bias, float* __restrict__ C,
    int M, int bm, int bn, const int* __restrict__ omask)
{
    int tid  = threadIdx.x;
    int lane = tid & 31, warp = tid >> 5;
    int wm = (warp & 3) * 16, wn = (warp >> 2) * 32;
    int ld4 = lane >> 2, lp4 = lane & 3;

    float acc[4][4];
#pragma unroll
    for (int i = 0; i < 4; i++)
#pragma unroll
        for (int j = 0; j < 4; j++) acc[i][j] = 0.f;

    gemm_load_stage(S, 0, 0, AH, AL, WH, WL, bm, bn, M);

    for (int kt = 0; kt < 8; kt++) {
        int s = kt & 1;
        if (kt < 7) {
            gemm_load_stage(S, s ^ 1, kt + 1, AH, AL, WH, WL, bm, bn, M);
            cpa_wait<1>();
        } else {
            cpa_wait<0>();
        }
        __syncthreads();
#pragma unroll
        for (int ks = 0; ks < 2; ks++) {
            int kpb = ks * 8;
            unsigned aH0 = S.AsH[s][wm+ld4  ][kpb+lp4  ];
            unsigned aH1 = S.AsH[s][wm+ld4+8][kpb+lp4  ];
            unsigned aH2 = S.AsH[s][wm+ld4  ][kpb+lp4+4];
            unsigned aH3 = S.AsH[s][wm+ld4+8][kpb+lp4+4];
            unsigned aL0 = S.AsL[s][wm+ld4  ][kpb+lp4  ];
            unsigned aL1 = S.AsL[s][wm+ld4+8][kpb+lp4  ];
            unsigned aL2 = S.AsL[s][wm+ld4  ][kpb+lp4+4];
            unsigned aL3 = S.AsL[s][wm+ld4+8][kpb+lp4+4];
#pragma unroll
            for (int nf = 0; nf < 4; nf++) {
                int col = wn + nf*8 + ld4;
                unsigned bH0 = S.BsH[s][kpb+lp4  ][col];
                unsigned bH1 = S.BsH[s][kpb+lp4+4][col];
                unsigned bL0 = S.BsL[s][kpb+lp4  ][col];
                unsigned bL1 = S.BsL[s][kpb+lp4+4][col];
                mma_bf16(acc[nf][0], acc[nf][1], acc[nf][2], acc[nf][3],
                         aH0, aH1, aH2, aH3, bH0, bH1);
                mma_bf16(acc[nf][0], acc[nf][1], acc[nf][2], acc[nf][3],
                         aL0, aL1, aL2, aL3, bH0, bH1);
                mma_bf16(acc[nf][0], acc[nf][1], acc[nf][2], acc[nf][3],
                         aH0, aH1, aH2, aH3, bL0, bL1);
            }
        }
        __syncthreads();
    }

    int r0 = bm + wm + ld4, r1 = r0 + 8;
#pragma unroll
    for (int nf = 0; nf < 4; nf++) {
        int n = bn + wn + nf*8 + lp4*2;
        float b0v = __ldg(bias + n), b1v = __ldg(bias + n + 1);
        if (r0 < M) {
            float2 o = make_float2(acc[nf][0] + b0v, acc[nf][1] + b1v);
            if (omask && omask[r0] != 0) o = make_float2(0.f, 0.f);
            *(float2*)(C + (long)r0*256 + n) = o;
        }
        if (r1 < M) {
            float2 o = make_float2(acc[nf][2] + b0v, acc[nf][3] + b1v);
            if (omask && omask[r1] != 0) o = make_float2(0.f, 0.f);
            *(float2*)(C + (long)r1*256 + n) = o;
        }
    }
}

// ---------------- fused: q-GEMM blocks + sampling blocks ---------------------
#define GQ_BLOCKS  (((BQ + 63)/64) * 4)      // 29*4 = 116
#define SAMP_BLOCKS 772

__constant__ int c_H[4] = {112, 56, 28, 14};
__constant__ int c_W[4] = {200, 100, 50, 25};

__global__ __launch_bounds__(256) void fused_qsample_kernel(
    const float* __restrict__ bq,
    const float* __restrict__ f0, const float* __restrict__ f1,
    const float* __restrict__ f2, const float* __restrict__ f3)
{
    __shared__ GemmSmem S;
    int bid = blockIdx.x;
    if (bid < GQ_BLOCKS) {
        int bm = (bid >> 2) * 64;
        int bn = (bid & 3) * 64;
        gemm_core(S, g_aqH, g_aqL, g_WH[0], g_WL[0], bq, g_q, BQ, bm, bn, nullptr);
        return;
    }
    // -------- sampling: one point per block-iteration, 256 threads=channels --
    int cnt = g_count;
    const float* fp[4] = {f0, f1, f2, f3};
    int t = threadIdx.x;
    for (int i = bid - GQ_BLOCKS; i < cnt; i += SAMP_BLOCKS) {
        float4 pc = g_projc[i];
        float X = pc.x, Y = pc.y;
        int cam = (int)pc.z;

        int   off[4][4];
        float wei[4][4];
#pragma unroll
        for (int l = 0; l < 4; l++) {
            int H = c_H[l], W = c_W[l];
            float fx = X * ((float)W / 800.0f);
            float fy = Y * ((float)H / 448.0f);
            float gx = fminf(fmaxf(fx / (float)(W-1) * 2.0f - 1.0f, -10.f), 10.f);
            float gy = fminf(fmaxf(fy / (float)(H-1) * 2.0f - 1.0f, -10.f), 10.f);
            float px = (gx + 1.0f) * 0.5f * (float)(W-1);
            float py = (gy + 1.0f) * 0.5f * (float)(H-1);
            float x0f = floorf(px), y0f = floorf(py);
            int x0 = (int)x0f, y0 = (int)y0f;
            float wx = px - x0f, wy = py - y0f;
            bool vx0 = (x0 >= 0)   && (x0 < W);
            bool vx1 = (x0+1 >= 0) && (x0+1 < W);
            bool vy0 = (y0 >= 0)   && (y0 < H);
            bool vy1 = (y0+1 >= 0) && (y0+1 < H);
            int xc0 = min(max(x0, 0), W-1),  xc1 = min(max(x0+1, 0), W-1);
            int yc0 = min(max(y0, 0), H-1),  yc1 = min(max(y0+1, 0), H-1);
            off[l][0] = (vy0 && vx0) ? yc0*W + xc0 : -1;
            off[l][1] = (vy0 && vx1) ? yc0*W + xc1 : -1;
            off[l][2] = (vy1 && vx0) ? yc1*W + xc0 : -1;
            off[l][3] = (vy1 && vx1) ? yc1*W + xc1 : -1;
            wei[l][0] = (1.f-wx)*(1.f-wy);
            wei[l][1] = wx*(1.f-wy);
            wei[l][2] = (1.f-wx)*wy;
            wei[l][3] = wx*wy;
        }
        float acc = 0.f;
#pragma unroll
        for (int l = 0; l < 4; l++) {
            int HW = c_H[l] * c_W[l];
            const float* base = fp[l] + (long)(cam*Cn + t) * HW;
#pragma unroll
            for (int r = 0; r < 4; r++) {
                int o = off[l][r];
                if (o >= 0) acc += __ldg(base + o) * wei[l][r];
            }
        }
        float val = acc * 0.25f;
        float other = __shfl_xor_sync(0xffffffffu, val, 1);
        if ((t & 1) == 0) {
            unsigned h, l;
            split2(val, other, h, l);
            g_msH[(long)i*128 + (t >> 1)] = h;
            g_msL[(long)i*128 + (t >> 1)] = l;
        }
    }
}

// ---------------- v-GEMM (dynamic M) -----------------------------------------
__global__ __launch_bounds__(256) void vgemm_kernel(const float* __restrict__ bv) {
    __shared__ GemmSmem S;
    int M = g_count;
    int bm = blockIdx.y * 64;
    if (bm >= M) return;
    int bn = blockIdx.x * 64;
    gemm_core(S, g_msH, g_msL, g_WH[1], g_WL[1], bv, g_v, M, bm, bn, nullptr);
}

// ---------------- maxfuse: max over cams + relu-fuse + pack ------------------
__global__ void maxfuse_kernel(const float* __restrict__ bv) {
    int bq = blockIdx.x;
    int t = threadIdx.x;          // 128 threads, channels 2t,2t+1
    int b = bq / Qn, q = bq % Qn;
    __shared__ int slots[Ncam];
    if (t < Ncam) slots[t] = g_map[(b*Ncam + t)*Qn + q];
    __syncthreads();
    int c0 = 2*t, c1 = 2*t + 1;
    float bv0 = __ldg(bv + c0), bv1 = __ldg(bv + c1);
    float m0 = -FLT_MAX, m1 = -FLT_MAX;
#pragma unroll
    for (int n = 0; n < Ncam; n++) {
        int s = slots[n];
        float v0 = (s >= 0) ? g_v[(long)s*Cn + c0] : bv0;
        float v1 = (s >= 0) ? g_v[(long)s*Cn + c1] : bv1;
        m0 = fmaxf(m0, v0);
        m1 = fmaxf(m1, v1);
    }
    float q0 = g_q[(long)bq*Cn + c0], q1 = g_q[(long)bq*Cn + c1];
    float f0 = fmaxf(q0 + m0, 0.f) + q0;
    float f1 = fmaxf(q1 + m1, 0.f) + q1;
    unsigned h, l;
    split2(f0, f1, h, l);
    g_fuH[(long)bq*128 + t] = h;
    g_fuL[(long)bq*128 + t] = l;
}

// ---------------- o-GEMM -----------------------------------------------------
__global__ __launch_bounds__(256) void ogemm_kernel(
    const float* __restrict__ bo, float* __restrict__ out,
    const int* __restrict__ mask)
{
    __shared__ GemmSmem S;
    int bm = blockIdx.y * 64;
    int bn = blockIdx.x * 64;
    gemm_core(S, g_fuH, g_fuL, g_WH[2], g_WL[2], bo, out, BQ, bm, bn, mask);
}

// ---------------- launch ------------------------------------------------------
extern "C" void kernel_launch(void* const* d_in, const int* in_sizes, int n_in,
                              void* d_out, int out_size) {
    const float* query  = (const float*)d_in[0];
    const float* refpts = (const float*)d_in[1];
    const int*   mask   = (const int*)  d_in[2];
    const float* intr   = (const float*)d_in[3];
    const float* ext    = (const float*)d_in[4];
    const float* f0     = (const float*)d_in[5];
    const float* f1     = (const float*)d_in[6];
    const float* f2     = (const float*)d_in[7];
    const float* f3     = (const float*)d_in[8];
    const float* bq     = (const float*)d_in[10];
    const float* Wq     = (const float*)d_in[9];
    const float* Wv     = (const float*)d_in[11];
    const float* bv     = (const float*)d_in[12];
    const float* Wo     = (const float*)d_in[13];
    const float* bo     = (const float*)d_in[14];

    invert_kernel<<<1, 32>>>(ext);
    prep_kernel<<<(PREP_W + PREP_Q + 255)/256, 256>>>(Wq, Wv, Wo, query);
    project_kernel<<<(NP + 127)/128, 128>>>(refpts, mask, intr);
    fused_qsample_kernel<<<GQ_BLOCKS + SAMP_BLOCKS, 256>>>(bq, f0, f1, f2, f3);
    vgemm_kernel<<<dim3(4, (NP + 63)/64), 256>>>(bv);
    maxfuse_kernel<<<BQ, 128>>>(bv);
    ogemm_kernel<<<dim3(4, (BQ + 63)/64), 256>>>(bo, (float*)d_out, mask);
}

// round 9
// speedup vs baseline: 1.5157x; 1.0004x over previous
#include <cuda_runtime.h>
#include <cuda_bf16.h>
#include <math.h>
#include <float.h>

#define Bb   2
#define Qn   900
#define Cn   256
#define Ncam 6
#define NP   (Bb*Ncam*Qn)   // 10800
#define BQ   (Bb*Qn)        // 1800

// ---------------- scratch (static device globals; no allocation) -------------
__device__ float  g_inv[Bb*Ncam*16];
__device__ int    g_count;
__device__ int    g_map[NP];
__device__ float4 g_projc[NP];
__device__ float  g_v [NP*Cn];
__device__ float  g_q [BQ*Cn];
// packed split-bf16 operands: word (row,kp) packs bf16(x[2kp]),bf16(x[2kp+1])
__device__ unsigned g_WH[3][128*256], g_WL[3][128*256];   // weights [kpair][n]
__device__ unsigned g_aqH[BQ*128],  g_aqL[BQ*128];        // query   [m][kpair]
__device__ unsigned g_msH[NP*128],  g_msL[NP*128];        // sampled [m][kpair]
__device__ unsigned g_fuH[BQ*128],  g_fuL[BQ*128];        // fused   [m][kpair]

// ---------------- helpers ----------------------------------------------------
__device__ __forceinline__ void split2(float a, float b, unsigned& h, unsigned& l) {
    __nv_bfloat16 ah = __float2bfloat16(a), bh = __float2bfloat16(b);
    __nv_bfloat16 al = __float2bfloat16(a - __bfloat162float(ah));
    __nv_bfloat16 bl = __float2bfloat16(b - __bfloat162float(bh));
    h = (unsigned)__bfloat16_as_ushort(ah) | ((unsigned)__bfloat16_as_ushort(bh) << 16);
    l = (unsigned)__bfloat16_as_ushort(al) | ((unsigned)__bfloat16_as_ushort(bl) << 16);
}

__device__ __forceinline__ void cpa16(void* dst_smem, const void* src) {
    unsigned d = (unsigned)__cvta_generic_to_shared(dst_smem);
    asm volatile("cp.async.cg.shared.global [%0], [%1], 16;" :: "r"(d), "l"(src));
}
__device__ __forceinline__ void cpa_commit() { asm volatile("cp.async.commit_group;"); }
template<int N> __device__ __forceinline__ void cpa_wait() {
    asm volatile("cp.async.wait_group %0;" :: "n"(N));
}

__device__ __forceinline__ void mma_bf16(float& d0, float& d1, float& d2, float& d3,
    unsigned a0, unsigned a1, unsigned a2, unsigned a3, unsigned b0, unsigned b1) {
    asm volatile("mma.sync.aligned.m16n8k16.row.col.f32.bf16.bf16.f32 "
        "{%0,%1,%2,%3}, {%4,%5,%6,%7}, {%8,%9}, {%0,%1,%2,%3};"
        : "+f"(d0), "+f"(d1), "+f"(d2), "+f"(d3)
        : "r"(a0), "r"(a1), "r"(a2), "r"(a3), "r"(b0), "r"(b1));
}

// ---------------- K1: batched 4x4 inverse ------------------------------------
__global__ void invert_kernel(const float* __restrict__ ext) {
    int t = threadIdx.x;
    if (t == 0) g_count = 0;
    if (t >= Bb*Ncam) return;
    const float* E = ext + t*16;
    double a[4][8];
    for (int i = 0; i < 4; i++)
        for (int j = 0; j < 4; j++) { a[i][j] = (double)E[i*4+j]; a[i][4+j] = (i==j) ? 1.0 : 0.0; }
    for (int c = 0; c < 4; c++) {
        int p = c; double mv = fabs(a[c][c]);
        for (int r = c+1; r < 4; r++) { double v = fabs(a[r][c]); if (v > mv) { mv = v; p = r; } }
        if (p != c) for (int j = 0; j < 8; j++) { double tmp = a[c][j]; a[c][j] = a[p][j]; a[p][j] = tmp; }
        double ip = 1.0 / a[c][c];
        for (int j = 0; j < 8; j++) a[c][j] *= ip;
        for (int r = 0; r < 4; r++) if (r != c) {
            double f = a[r][c];
            for (int j = 0; j < 8; j++) a[r][j] -= f * a[c][j];
        }
    }
    for (int i = 0; i < 4; i++)
        for (int j = 0; j < 4; j++) {
            float f = (float)a[i][4+j];
            if (isnan(f)) f = 0.0f;
            else if (isinf(f)) f = (f > 0.f) ? 1e6f : -1e6f;
            g_inv[t*16 + i*4 + j] = f;
        }
}

// ---------------- prep: pack weights + query ---------------------------------
#define PREP_W (3*128*256)
#define PREP_Q (BQ*128)
__global__ void prep_kernel(const float* __restrict__ Wq, const float* __restrict__ Wv,
                            const float* __restrict__ Wo, const float* __restrict__ query) {
    int idx = blockIdx.x * blockDim.x + threadIdx.x;
    if (idx < PREP_W) {
        int w   = idx / (128*256);
        int rem = idx % (128*256);
        int kp  = rem / 256;
        int n   = rem % 256;
        const float* W = (w==0) ? Wq : ((w==1) ? Wv : Wo);
        unsigned h, l;
        split2(W[n*256 + kp*2], W[n*256 + kp*2 + 1], h, l);
        g_WH[w][rem] = h; g_WL[w][rem] = l;
    } else if (idx < PREP_W + PREP_Q) {
        int j = idx - PREP_W;
        int m = j >> 7, kp = j & 127;
        unsigned h, l;
        split2(query[m*256 + kp*2], query[m*256 + kp*2 + 1], h, l);
        g_aqH[j] = h; g_aqL[j] = l;
    }
}

// ---------------- K2: project + candidate compaction -------------------------
__global__ void project_kernel(const float* __restrict__ refpts,
                               const int*   __restrict__ mask,
                               const float* __restrict__ intr) {
    int p = blockIdx.x * blockDim.x + threadIdx.x;
    if (p >= NP) return;
    int b = p / (Ncam*Qn);
    int n = (p / Qn) % Ncam;
    int q = p % Qn;
    int bq = b*Qn + q;
    if (mask[bq] != 0) { g_map[p] = -1; return; }

    float r0 = refpts[bq*3+0] * 102.4f - 51.2f;
    float r1 = refpts[bq*3+1] * 102.4f - 51.2f;
    float r2 = refpts[bq*3+2] * 102.4f - 51.2f;

    const float* iv = g_inv + (b*Ncam + n)*16;
    float p0 = iv[0]*r0 + iv[1]*r1 + iv[2]*r2  + iv[3];
    float p1 = iv[4]*r0 + iv[5]*r1 + iv[6]*r2  + iv[7];
    float p2 = iv[8]*r0 + iv[9]*r1 + iv[10]*r2 + iv[11];

    float depth = p2;
    if (isnan(depth)) depth = 10.0f;
    else if (isinf(depth)) depth = (depth > 0.f) ? 100.0f : -100.0f;
    bool invalid = depth < 1.5f;
    float ds = fmaxf(depth, 1.5f);

    float cx = p0 / ds, cy = p1 / ds, cz = p2 / ds;
    const float* Km = intr + (b*Ncam + n)*9;
    float ix = Km[0]*cx + Km[1]*cy + Km[2]*cz;
    float iy = Km[3]*cx + Km[4]*cy + Km[5]*cz;
    ix = fminf(fmaxf(ix, -3000.f), 3000.f);
    iy = fminf(fmaxf(iy, -3000.f), 3000.f);

    bool cand = !invalid && (ix >= -32.f) && (ix < 800.f) && (iy >= -32.f) && (iy < 448.f);
    int slot = -1;
    if (cand) {
        slot = atomicAdd(&g_count, 1);
        g_projc[slot] = make_float4(ix, iy, (float)(b*Ncam + n), 0.f);
    }
    g_map[p] = slot;
}

// ---------------- pipelined tensor-core GEMM core ----------------------------
// C[M,256] = unpack(AH,AL) @ unpack(W)^T + bias.  BM=64,BN=64,BK=32, 256 thr.
// A packed [m][128 kpair], W packed [kpair][256]. 2-stage cp.async pipeline.
struct GemmSmem {
    unsigned AsH[2][64][20], AsL[2][64][20];
    unsigned BsH[2][16][72], BsL[2][16][72];
};

__device__ __forceinline__ void gemm_load_stage(
    GemmSmem& S, int s, int kt,
    const unsigned* __restrict__ AH, const unsigned* __restrict__ AL,
    const unsigned* __restrict__ WH, const unsigned* __restrict__ WL,
    int bm, int bn, int M)
{
    int tid = threadIdx.x;
    // A: 256 chunks of 16B each for H and L
    {
        int m = tid >> 2, q = tid & 3;
        int row = min(bm + m, M-1);
        long src = (long)row*128 + kt*16 + q*4;
        cpa16(&S.AsH[s][m][q*4], AH + src);
        cpa16(&S.AsL[s][m][q*4], AL + src);
    }
    // B: 256 chunks for H, 256 for L
    {
        int kpr = tid >> 4, q = tid & 15;
        long src = (long)(kt*16 + kpr)*256 + bn + q*4;
        cpa16(&S.BsH[s][kpr][q*4], WH + src);
        cpa16(&S.BsL[s][kpr][q*4], WL + src);
    }
    cpa_commit();
}

__device__ __forceinline__ void gemm_core(
    GemmSmem& S,
    const unsigned* __restrict__ AH, const unsigned* __restrict__ AL,
    const unsigned* __restrict__ WH, const unsigned* __restrict__ WL,
    const float* __restrict__ bias, float* __restrict__ C,
    int M, int bm, int bn, const int* __restrict__ omask)
{
    int tid  = threadIdx.x;
    int lane = tid & 31, warp = tid >> 5;
    int wm = (warp & 3) * 16, wn = (warp >> 2) * 32;
    int ld4 = lane >> 2, lp4 = lane & 3;

    float acc[4][4];
#pragma unroll
    for (int i = 0; i < 4; i++)
#pragma unroll
        for (int j = 0; j < 4; j++) acc[i][j] = 0.f;

    gemm_load_stage(S, 0, 0, AH, AL, WH, WL, bm, bn, M);

    for (int kt = 0; kt < 8; kt++) {
        int s = kt & 1;
        if (kt < 7) {
            gemm_load_stage(S, s ^ 1, kt + 1, AH, AL, WH, WL, bm, bn, M);
            cpa_wait<1>();
        } else {
            cpa_wait<0>();
        }
        __syncthreads();
#pragma unroll
        for (int ks = 0; ks < 2; ks++) {
            int kpb = ks * 8;
            unsigned aH0 = S.AsH[s][wm+ld4  ][kpb+lp4  ];
            unsigned aH1 = S.AsH[s][wm+ld4+8][kpb+lp4  ];
            unsigned aH2 = S.AsH[s][wm+ld4  ][kpb+lp4+4];
            unsigned aH3 = S.AsH[s][wm+ld4+8][kpb+lp4+4];
            unsigned aL0 = S.AsL[s][wm+ld4  ][kpb+lp4  ];
            unsigned aL1 = S.AsL[s][wm+ld4+8][kpb+lp4  ];
            unsigned aL2 = S.AsL[s][wm+ld4  ][kpb+lp4+4];
            unsigned aL3 = S.AsL[s][wm+ld4+8][kpb+lp4+4];
#pragma unroll
            for (int nf = 0; nf < 4; nf++) {
                int col = wn + nf*8 + ld4;
                unsigned bH0 = S.BsH[s][kpb+lp4  ][col];
                unsigned bH1 = S.BsH[s][kpb+lp4+4][col];
                unsigned bL0 = S.BsL[s][kpb+lp4  ][col];
                unsigned bL1 = S.BsL[s][kpb+lp4+4][col];
                mma_bf16(acc[nf][0], acc[nf][1], acc[nf][2], acc[nf][3],
                         aH0, aH1, aH2, aH3, bH0, bH1);
                mma_bf16(acc[nf][0], acc[nf][1], acc[nf][2], acc[nf][3],
                         aL0, aL1, aL2, aL3, bH0, bH1);
                mma_bf16(acc[nf][0], acc[nf][1], acc[nf][2], acc[nf][3],
                         aH0, aH1, aH2, aH3, bL0, bL1);
            }
        }
        __syncthreads();
    }

    int r0 = bm + wm + ld4, r1 = r0 + 8;
#pragma unroll
    for (int nf = 0; nf < 4; nf++) {
        int n = bn + wn + nf*8 + lp4*2;
        float b0v = __ldg(bias + n), b1v = __ldg(bias + n + 1);
        if (r0 < M) {
            float2 o = make_float2(acc[nf][0] + b0v, acc[nf][1] + b1v);
            if (omask && omask[r0] != 0) o = make_float2(0.f, 0.f);
            *(float2*)(C + (long)r0*256 + n) = o;
        }
        if (r1 < M) {
            float2 o = make_float2(acc[nf][2] + b0v, acc[nf][3] + b1v);
            if (omask && omask[r1] != 0) o = make_float2(0.f, 0.f);
            *(float2*)(C + (long)r1*256 + n) = o;
        }
    }
}

// ---------------- fused: q-GEMM blocks + sampling blocks ---------------------
#define GQ_BLOCKS  (((BQ + 63)/64) * 4)      // 29*4 = 116
#define SAMP_BLOCKS 772

__constant__ int c_H[4] = {112, 56, 28, 14};
__constant__ int c_W[4] = {200, 100, 50, 25};

__global__ __launch_bounds__(256) void fused_qsample_kernel(
    const float* __restrict__ bq,
    const float* __restrict__ f0, const float* __restrict__ f1,
    const float* __restrict__ f2, const float* __restrict__ f3)
{
    __shared__ GemmSmem S;
    int bid = blockIdx.x;
    if (bid < GQ_BLOCKS) {
        int bm = (bid >> 2) * 64;
        int bn = (bid & 3) * 64;
        gemm_core(S, g_aqH, g_aqL, g_WH[0], g_WL[0], bq, g_q, BQ, bm, bn, nullptr);
        return;
    }
    // -------- sampling: one point per block-iteration, 256 threads=channels --
    int cnt = g_count;
    const float* fp[4] = {f0, f1, f2, f3};
    int t = threadIdx.x;
    for (int i = bid - GQ_BLOCKS; i < cnt; i += SAMP_BLOCKS) {
        float4 pc = g_projc[i];
        float X = pc.x, Y = pc.y;
        int cam = (int)pc.z;

        int   off[4][4];
        float wei[4][4];
#pragma unroll
        for (int l = 0; l < 4; l++) {
            int H = c_H[l], W = c_W[l];
            float fx = X * ((float)W / 800.0f);
            float fy = Y * ((float)H / 448.0f);
            float gx = fminf(fmaxf(fx / (float)(W-1) * 2.0f - 1.0f, -10.f), 10.f);
            float gy = fminf(fmaxf(fy / (float)(H-1) * 2.0f - 1.0f, -10.f), 10.f);
            float px = (gx + 1.0f) * 0.5f * (float)(W-1);
            float py = (gy + 1.0f) * 0.5f * (float)(H-1);
            float x0f = floorf(px), y0f = floorf(py);
            int x0 = (int)x0f, y0 = (int)y0f;
            float wx = px - x0f, wy = py - y0f;
            bool vx0 = (x0 >= 0)   && (x0 < W);
            bool vx1 = (x0+1 >= 0) && (x0+1 < W);
            bool vy0 = (y0 >= 0)   && (y0 < H);
            bool vy1 = (y0+1 >= 0) && (y0+1 < H);
            int xc0 = min(max(x0, 0), W-1),  xc1 = min(max(x0+1, 0), W-1);
            int yc0 = min(max(y0, 0), H-1),  yc1 = min(max(y0+1, 0), H-1);
            off[l][0] = (vy0 && vx0) ? yc0*W + xc0 : -1;
            off[l][1] = (vy0 && vx1) ? yc0*W + xc1 : -1;
            off[l][2] = (vy1 && vx0) ? yc1*W + xc0 : -1;
            off[l][3] = (vy1 && vx1) ? yc1*W + xc1 : -1;
            wei[l][0] = (1.f-wx)*(1.f-wy);
            wei[l][1] = wx*(1.f-wy);
            wei[l][2] = (1.f-wx)*wy;
            wei[l][3] = wx*wy;
        }
        float acc = 0.f;
#pragma unroll
        for (int l = 0; l < 4; l++) {
            int HW = c_H[l] * c_W[l];
            const float* base = fp[l] + (long)(cam*Cn + t) * HW;
#pragma unroll
            for (int r = 0; r < 4; r++) {
                int o = off[l][r];
                if (o >= 0) acc += __ldg(base + o) * wei[l][r];
            }
        }
        float val = acc * 0.25f;
        float other = __shfl_xor_sync(0xffffffffu, val, 1);
        if ((t & 1) == 0) {
            unsigned h, l;
            split2(val, other, h, l);
            g_msH[(long)i*128 + (t >> 1)] = h;
            g_msL[(long)i*128 + (t >> 1)] = l;
        }
    }
}

// ---------------- v-GEMM (dynamic M) -----------------------------------------
__global__ __launch_bounds__(256) void vgemm_kernel(const float* __restrict__ bv) {
    __shared__ GemmSmem S;
    int M = g_count;
    int bm = blockIdx.y * 64;
    if (bm >= M) return;
    int bn = blockIdx.x * 64;
    gemm_core(S, g_msH, g_msL, g_WH[1], g_WL[1], bv, g_v, M, bm, bn, nullptr);
}

// ---------------- maxfuse: max over cams + relu-fuse + pack ------------------
__global__ void maxfuse_kernel(const float* __restrict__ bv) {
    int bq = blockIdx.x;
    int t = threadIdx.x;          // 128 threads, channels 2t,2t+1
    int b = bq / Qn, q = bq % Qn;
    __shared__ int slots[Ncam];
    if (t < Ncam) slots[t] = g_map[(b*Ncam + t)*Qn + q];
    __syncthreads();
    int c0 = 2*t, c1 = 2*t + 1;
    float bv0 = __ldg(bv + c0), bv1 = __ldg(bv + c1);
    float m0 = -FLT_MAX, m1 = -FLT_MAX;
#pragma unroll
    for (int n = 0; n < Ncam; n++) {
        int s = slots[n];
        float v0 = (s >= 0) ? g_v[(long)s*Cn + c0] : bv0;
        float v1 = (s >= 0) ? g_v[(long)s*Cn + c1] : bv1;
        m0 = fmaxf(m0, v0);
        m1 = fmaxf(m1, v1);
    }
    float q0 = g_q[(long)bq*Cn + c0], q1 = g_q[(long)bq*Cn + c1];
    float f0 = fmaxf(q0 + m0, 0.f) + q0;
    float f1 = fmaxf(q1 + m1, 0.f) + q1;
    unsigned h, l;
    split2(f0, f1, h, l);
    g_fuH[(long)bq*128 + t] = h;
    g_fuL[(long)bq*128 + t] = l;
}

// ---------------- o-GEMM -----------------------------------------------------
__global__ __launch_bounds__(256) void ogemm_kernel(
    const float* __restrict__ bo, float* __restrict__ out,
    const int* __restrict__ mask)
{
    __shared__ GemmSmem S;
    int bm = blockIdx.y * 64;
    int bn = blockIdx.x * 64;
    gemm_core(S, g_fuH, g_fuL, g_WH[2], g_WL[2], bo, out, BQ, bm, bn, mask);
}

// ---------------- launch ------------------------------------------------------
extern "C" void kernel_launch(void* const* d_in, const int* in_sizes, int n_in,
                              void* d_out, int out_size) {
    const float* query  = (const float*)d_in[0];
    const float* refpts = (const float*)d_in[1];
    const int*   mask   = (const int*)  d_in[2];
    const float* intr   = (const float*)d_in[3];
    const float* ext    = (const float*)d_in[4];
    const float* f0     = (const float*)d_in[5];
    const float* f1     = (const float*)d_in[6];
    const float* f2     = (const float*)d_in[7];
    const float* f3     = (const float*)d_in[8];
    const float* bq     = (const float*)d_in[10];
    const float* Wq     = (const float*)d_in[9];
    const float* Wv     = (const float*)d_in[11];
    const float* bv     = (const float*)d_in[12];
    const float* Wo     = (const float*)d_in[13];
    const float* bo     = (const float*)d_in[14];

    invert_kernel<<<1, 32>>>(ext);
    prep_kernel<<<(PREP_W + PREP_Q + 255)/256, 256>>>(Wq, Wv, Wo, query);
    project_kernel<<<(NP + 127)/128, 128>>>(refpts, mask, intr);
    fused_qsample_kernel<<<GQ_BLOCKS + SAMP_BLOCKS, 256>>>(bq, f0, f1, f2, f3);
    vgemm_kernel<<<dim3(4, (NP + 63)/64), 256>>>(bv);
    maxfuse_kernel<<<BQ, 128>>>(bv);
    ogemm_kernel<<<dim3(4, (BQ + 63)/64), 256>>>(bo, (float*)d_out, mask);
}